// round 4
// baseline (speedup 1.0000x reference)
#include <cuda_runtime.h>
#include <cstdint>

#define NB 256   // batch
#define ND 16    // manifold dim
#define NH 128   // hidden
#define R2H 256  // 2H

// ---- scratch (device globals; no allocation) ----
__device__ float g_metric[NB * 256];          // metric[b][i*16+j]
__device__ float g_PB[NB * 256];              // points@rW1[0:16] + rb1
__device__ float g_M1[NB * ND * 256];         // M1[b][i][o]
__device__ float g_M2[NB * ND * 256];         // M2[b][j][o]
__device__ float g_Spart[NB * ND * 256];      // per-(b,i) partial hidden sums

// single-MUFU tanh
__device__ __forceinline__ float tanh_fast(float x) {
    float y;
    asm("tanh.approx.f32 %0, %1;" : "=f"(y) : "f"(x));
    return y;
}

// ============================================================================
// K1: metric + PB + M1/M2.  grid=NB, 1024 threads.
// Group g = t>>8 (0..3), lane o = t&255. Serial GEMM chains split 4-way.
// ============================================================================
__global__ __launch_bounds__(1024) void k_metric(
    const float* __restrict__ points,
    const float* __restrict__ mW1, const float* __restrict__ mb1,
    const float* __restrict__ mW2, const float* __restrict__ mb2,
    const float* __restrict__ rW1, const float* __restrict__ rb1)
{
    int b = blockIdx.x;
    int t = threadIdx.x;
    int g = t >> 8, o = t & 255;

    __shared__ float pts[ND];
    __shared__ float mh[NH];
    __shared__ float part[4][256];
    __shared__ float met[256];

    if (t < ND) pts[t] = points[b * ND + t];
    __syncthreads();

    // hidden layer of metric net (only 128 threads needed)
    if (t < NH) {
        float a = mb1[t];
        #pragma unroll
        for (int p = 0; p < ND; p++) a = fmaf(pts[p], mW1[p * NH + t], a);
        mh[t] = fmaxf(a, 0.0f);
    }
    __syncthreads();

    // mraw[o] = mb2[o] + sum_h mh[h]*mW2[h][o]  -- 4-way split over h
    {
        float a = 0.0f;
        int h0 = g * 32;
        #pragma unroll
        for (int h = 0; h < 32; h++)
            a = fmaf(mh[h0 + h], mW2[(h0 + h) * 256 + o], a);
        part[g][o] = a;
    }
    __syncthreads();

    if (t < 256) {
        float a = mb2[t] + part[0][t] + part[1][t] + part[2][t] + part[3][t];
        part[0][t] = a;   // stash raw
    }
    __syncthreads();

    if (t < 256) {
        int i = t >> 4, j = t & 15;
        float m = 0.5f * (part[0][i * 16 + j] + part[0][j * 16 + i])
                + (i == j ? 1e-6f : 0.0f);
        met[t] = m;
        g_metric[b * 256 + t] = m;
        // PB
        float a = rb1[t];
        #pragma unroll
        for (int p = 0; p < ND; p++) a = fmaf(pts[p], rW1[p * 256 + t], a);
        g_PB[b * 256 + t] = a;
    }
    __syncthreads();

    // M1/M2: group g owns i in [4g, 4g+4)
    {
        float rwA[ND], rwB[ND];
        #pragma unroll
        for (int p = 0; p < ND; p++) {
            rwA[p] = rW1[(16 + p) * 256 + o];
            rwB[p] = rW1[(32 + p) * 256 + o];
        }
        #pragma unroll
        for (int ii = 0; ii < 4; ii++) {
            int i0 = g * 4 + ii;
            float a1 = 0.0f, a2 = 0.0f;
            #pragma unroll
            for (int p = 0; p < ND; p++) {
                float mv = met[i0 * 16 + p];
                a1 = fmaf(mv, rwA[p], a1);
                a2 = fmaf(mv, rwB[p], a2);
            }
            g_M1[(b * ND + i0) * 256 + o] = a1;
            g_M2[(b * ND + i0) * 256 + o] = a2;
        }
    }
}

// ============================================================================
// K2: main fused kernel (exact R2 structure). One block per (i, b); 256 thr.
// ============================================================================
__global__ __launch_bounds__(256) void k_main(
    const float* __restrict__ cW1, const float* __restrict__ cb1,
    const float* __restrict__ cW2, const float* __restrict__ cb2,
    const float* __restrict__ rW1)
{
    int i = blockIdx.x;   // 0..15
    int b = blockIdx.y;   // 0..255
    int t = threadIdx.x;  // 0..255

    __shared__ float met[256];
    __shared__ float2 w0p[NH / 2], w1p[NH / 2], w2p[NH / 2], wbp[NH / 2], v2p[NH / 2];
    __shared__ __align__(16) float chs[256];

    met[t] = g_metric[b * 256 + t];
    if (t < NH / 2) {
        const float2* c0 = (const float2*)cW1;            // row 0
        const float2* c1 = (const float2*)(cW1 + NH);     // row 1
        const float2* c2 = (const float2*)(cW1 + 2 * NH); // row 2
        const float2* cb = (const float2*)cb1;
        const float2* v2 = (const float2*)cW2;
        w0p[t] = c0[t]; w1p[t] = c1[t]; w2p[t] = c2[t];
        wbp[t] = cb[t]; v2p[t] = v2[t];
    }
    __syncthreads();

    // ---- Stage A: christoffel for (i, j=t>>4, k=t&15) ----
    {
        int j = t >> 4, k = t & 15;
        float mij = met[i * 16 + j];
        float mjk = met[j * 16 + k];
        float mki = met[i * 16 + k];   // metric symmetric

        float acc0 = cb2[0], acc1 = 0.0f;
        #pragma unroll 8
        for (int q = 0; q < NH / 2; q++) {
            float2 w0 = w0p[q], w1 = w1p[q], w2 = w2p[q], wb = wbp[q], v2 = v2p[q];
            float xa = fmaf(mki, w2.x, fmaf(mjk, w1.x, fmaf(mij, w0.x, wb.x)));
            float xb = fmaf(mki, w2.y, fmaf(mjk, w1.y, fmaf(mij, w0.y, wb.y)));
            acc0 = fmaf(v2.x, tanh_fast(xa), acc0);
            acc1 = fmaf(v2.y, tanh_fast(xb), acc1);
        }
        chs[t] = acc0 + acc1;
    }
    __syncthreads();

    // ---- Stage B: hidden layer of ricci net, reduced over j ----
    {
        int o = t;
        const float* rW1c = rW1 + 48 * 256;
        float rw[ND];
        #pragma unroll
        for (int k = 0; k < ND; k++) rw[k] = rW1c[k * 256 + o];

        float pm = g_PB[b * 256 + o] + g_M1[(b * ND + i) * 256 + o];
        float s = 0.0f;
        #pragma unroll 4
        for (int j = 0; j < ND; j++) {
            float a = pm + g_M2[(b * ND + j) * 256 + o];
            const float4* chr = (const float4*)&chs[j * 16];
            #pragma unroll
            for (int q = 0; q < 4; q++) {
                float4 c = chr[q];
                a = fmaf(c.x, rw[4 * q + 0], a);
                a = fmaf(c.y, rw[4 * q + 1], a);
                a = fmaf(c.z, rw[4 * q + 2], a);
                a = fmaf(c.w, rw[4 * q + 3], a);
            }
            s += fmaxf(a, 0.0f);
        }
        g_Spart[(b * ND + i) * 256 + o] = s;   // deterministic partials
    }
}

// ============================================================================
// K3: reduce partials + output GEMM + symmetrize.  grid=NB, 1024 threads.
// ============================================================================
__global__ __launch_bounds__(1024) void k_final(
    const float* __restrict__ rW2, const float* __restrict__ rb2,
    float* __restrict__ out)
{
    int b = blockIdx.x;
    int t = threadIdx.x;
    int g = t >> 8, o = t & 255;

    __shared__ float part[4][256];
    __shared__ float Ss[256];

    // reduce Spart over i: group g sums i in [4g, 4g+4)
    {
        float s = 0.0f;
        #pragma unroll
        for (int ii = 0; ii < 4; ii++)
            s += g_Spart[(b * ND + g * 4 + ii) * 256 + o];
        part[g][o] = s;
    }
    __syncthreads();
    if (t < 256)
        Ss[t] = (part[0][t] + part[1][t] + part[2][t] + part[3][t]) * (1.0f / 256.0f);
    __syncthreads();

    // raw[o] = rb2[o] + sum_h Ss[h]*rW2[h][o]  -- 4-way split over h
    {
        float a = 0.0f;
        int h0 = g * 64;
        #pragma unroll
        for (int h = 0; h < 64; h++)
            a = fmaf(Ss[h0 + h], rW2[(h0 + h) * 256 + o], a);
        part[g][o] = a;
    }
    __syncthreads();

    if (t < 256) {
        // re-use Ss as raw buffer
        Ss[t] = rb2[t] + part[0][t] + part[1][t] + part[2][t] + part[3][t];
    }
    __syncthreads();

    if (t < 256) {
        int i = t >> 4, j = t & 15;
        out[b * 256 + t] = 0.5f * (Ss[i * 16 + j] + Ss[j * 16 + i]);
    }
}

// ============================================================================
extern "C" void kernel_launch(void* const* d_in, const int* in_sizes, int n_in,
                              void* d_out, int out_size)
{
    const float* points = (const float*)d_in[0];
    const float* mW1    = (const float*)d_in[1];
    const float* mb1    = (const float*)d_in[2];
    const float* mW2    = (const float*)d_in[3];
    const float* mb2    = (const float*)d_in[4];
    const float* cW1    = (const float*)d_in[5];
    const float* cb1    = (const float*)d_in[6];
    const float* cW2    = (const float*)d_in[7];
    const float* cb2    = (const float*)d_in[8];
    const float* rW1    = (const float*)d_in[9];
    const float* rb1    = (const float*)d_in[10];
    const float* rW2    = (const float*)d_in[11];
    const float* rb2    = (const float*)d_in[12];
    float* out = (float*)d_out;

    k_metric<<<NB, 1024>>>(points, mW1, mb1, mW2, mb2, rW1, rb1);
    dim3 grid2(ND, NB);
    k_main<<<grid2, 256>>>(cW1, cb1, cW2, cb2, rW1);
    k_final<<<NB, 1024>>>(rW2, rb2, out);
}

// round 5
// speedup vs baseline: 1.5693x; 1.5693x over previous
#include <cuda_runtime.h>
#include <cstdint>

#define NB 256   // batch
#define ND 16    // manifold dim
#define NH 128   // hidden
#define R2H 256  // 2H

// ---- scratch (device globals; no allocation) ----
__device__ float g_metric[NB * 256];          // metric[b][i*16+j]
__device__ float g_PB[NB * 256];              // points@rW1[0:16] + rb1
__device__ float g_M1[NB * ND * 256];         // M1[b][i][o]
__device__ float g_M2[NB * ND * 256];         // M2[b][j][o]
__device__ float g_Spart[NB * ND * 256];      // per-(b,i) partial hidden sums

// single-MUFU tanh
__device__ __forceinline__ float tanh_fast(float x) {
    float y;
    asm("tanh.approx.f32 %0, %1;" : "=f"(y) : "f"(x));
    return y;
}

// ============================================================================
// K1: metric + PB + M1/M2.  grid=NB, 1024 threads.
// Metric GEMM: 16 h-groups x 64 o-quads, float4 loads, short acc chains.
// ============================================================================
__global__ __launch_bounds__(1024) void k_metric(
    const float* __restrict__ points,
    const float* __restrict__ mW1, const float* __restrict__ mb1,
    const float* __restrict__ mW2, const float* __restrict__ mb2,
    const float* __restrict__ rW1, const float* __restrict__ rb1)
{
    int b = blockIdx.x;
    int t = threadIdx.x;

    __shared__ float pts[ND];
    __shared__ float mh[NH];
    __shared__ __align__(16) float part[16][256];   // 16KB
    __shared__ float met[256];

    if (t < ND) pts[t] = points[b * ND + t];
    __syncthreads();

    if (t < NH) {
        float a = mb1[t];
        #pragma unroll
        for (int p = 0; p < ND; p++) a = fmaf(pts[p], mW1[p * NH + t], a);
        mh[t] = fmaxf(a, 0.0f);
    }
    __syncthreads();

    // metric GEMM: group g=t>>6 handles h in [8g,8g+8); q=t&63 handles o-quad 4q
    {
        int g = t >> 6, q = t & 63;
        float4 acc = make_float4(0.f, 0.f, 0.f, 0.f);
        #pragma unroll
        for (int h = 0; h < 8; h++) {
            int hh = g * 8 + h;
            float4 w = *(const float4*)&mW2[hh * 256 + 4 * q];
            float m = mh[hh];
            acc.x = fmaf(m, w.x, acc.x);
            acc.y = fmaf(m, w.y, acc.y);
            acc.z = fmaf(m, w.z, acc.z);
            acc.w = fmaf(m, w.w, acc.w);
        }
        *(float4*)&part[g][4 * q] = acc;
    }
    __syncthreads();

    if (t < 256) {
        float a = mb2[t];
        #pragma unroll
        for (int g = 0; g < 16; g++) a += part[g][t];
        part[0][t] = a;  // thread t reads only column t, then writes column t: safe
    }
    __syncthreads();

    if (t < 256) {
        int i = t >> 4, j = t & 15;
        float m = 0.5f * (part[0][i * 16 + j] + part[0][j * 16 + i])
                + (i == j ? 1e-6f : 0.0f);
        met[t] = m;
        g_metric[b * 256 + t] = m;
        // PB
        float a = rb1[t];
        #pragma unroll
        for (int p = 0; p < ND; p++) a = fmaf(pts[p], rW1[p * 256 + t], a);
        g_PB[b * 256 + t] = a;
    }
    __syncthreads();

    // M1/M2: group g2=t>>8 owns i in [4*g2, 4*g2+4); o=t&255
    {
        int g2 = t >> 8, o = t & 255;
        float rwA[ND], rwB[ND];
        #pragma unroll
        for (int p = 0; p < ND; p++) {
            rwA[p] = rW1[(16 + p) * 256 + o];
            rwB[p] = rW1[(32 + p) * 256 + o];
        }
        #pragma unroll
        for (int ii = 0; ii < 4; ii++) {
            int i0 = g2 * 4 + ii;
            float a1 = 0.0f, a2 = 0.0f;
            #pragma unroll
            for (int p = 0; p < ND; p++) {
                float mv = met[i0 * 16 + p];
                a1 = fmaf(mv, rwA[p], a1);
                a2 = fmaf(mv, rwB[p], a2);
            }
            g_M1[(b * ND + i0) * 256 + o] = a1;
            g_M2[(b * ND + i0) * 256 + o] = a2;
        }
    }
}

// ============================================================================
// K2: main fused kernel. One block per (i, b); 256 threads.
// R2 scalar math; weights in float4-packed smem (3 LDS per 2 hiddens).
// ============================================================================
__global__ __launch_bounds__(256) void k_main(
    const float* __restrict__ cW1, const float* __restrict__ cb1,
    const float* __restrict__ cW2, const float* __restrict__ cb2,
    const float* __restrict__ rW1)
{
    int i = blockIdx.x;   // 0..15
    int b = blockIdx.y;   // 0..255
    int t = threadIdx.x;  // 0..255

    __shared__ float met[256];
    __shared__ __align__(16) float4 sAB[NH / 2];  // (w0a, w0b, w1a, w1b)
    __shared__ __align__(16) float4 sCD[NH / 2];  // (w2a, w2b, cba, cbb)
    __shared__ __align__(8)  float2 sV[NH / 2];   // (v2a, v2b)
    __shared__ __align__(16) float chs[256];

    met[t] = g_metric[b * 256 + t];
    if (t < NH / 2) {
        int q = t;
        sAB[q] = make_float4(cW1[2 * q], cW1[2 * q + 1],
                             cW1[NH + 2 * q], cW1[NH + 2 * q + 1]);
        sCD[q] = make_float4(cW1[2 * NH + 2 * q], cW1[2 * NH + 2 * q + 1],
                             cb1[2 * q], cb1[2 * q + 1]);
        sV[q]  = make_float2(cW2[2 * q], cW2[2 * q + 1]);
    }
    __syncthreads();

    // ---- Stage A: christoffel for (i, j=t>>4, k=t&15) ----
    {
        int j = t >> 4, k = t & 15;
        float mij = met[i * 16 + j];
        float mjk = met[j * 16 + k];
        float mki = met[i * 16 + k];   // metric symmetric

        float acc0 = cb2[0], acc1 = 0.0f;
        #pragma unroll 8
        for (int q = 0; q < NH / 2; q++) {
            float4 ab = sAB[q];
            float4 cd = sCD[q];
            float2 v  = sV[q];
            float xa = fmaf(mki, cd.x, fmaf(mjk, ab.z, fmaf(mij, ab.x, cd.z)));
            float xb = fmaf(mki, cd.y, fmaf(mjk, ab.w, fmaf(mij, ab.y, cd.w)));
            acc0 = fmaf(v.x, tanh_fast(xa), acc0);
            acc1 = fmaf(v.y, tanh_fast(xb), acc1);
        }
        chs[t] = acc0 + acc1;
    }
    __syncthreads();

    // ---- Stage B: hidden layer of ricci net, reduced over j ----
    {
        int o = t;
        const float* rW1c = rW1 + 48 * 256;
        float rw[ND];
        #pragma unroll
        for (int k = 0; k < ND; k++) rw[k] = rW1c[k * 256 + o];

        float pm = g_PB[b * 256 + o] + g_M1[(b * ND + i) * 256 + o];
        float s = 0.0f;
        #pragma unroll 4
        for (int j = 0; j < ND; j++) {
            float a = pm + g_M2[(b * ND + j) * 256 + o];
            const float4* chr = (const float4*)&chs[j * 16];
            #pragma unroll
            for (int q = 0; q < 4; q++) {
                float4 c = chr[q];
                a = fmaf(c.x, rw[4 * q + 0], a);
                a = fmaf(c.y, rw[4 * q + 1], a);
                a = fmaf(c.z, rw[4 * q + 2], a);
                a = fmaf(c.w, rw[4 * q + 3], a);
            }
            s += fmaxf(a, 0.0f);
        }
        g_Spart[(b * ND + i) * 256 + o] = s;   // deterministic partials
    }
}

// ============================================================================
// K3: reduce partials + output GEMM + symmetrize. grid=NB, 256 threads.
// 4 independent accumulator chains over the 256-h GEMM.
// ============================================================================
__global__ __launch_bounds__(256) void k_final(
    const float* __restrict__ rW2, const float* __restrict__ rb2,
    float* __restrict__ out)
{
    int b = blockIdx.x;
    int t = threadIdx.x;
    __shared__ float Ss[256];
    __shared__ float raw[256];

    float s = 0.0f;
    #pragma unroll
    for (int i = 0; i < ND; i++) s += g_Spart[(b * ND + i) * 256 + t];
    Ss[t] = s * (1.0f / 256.0f);
    __syncthreads();

    {
        float a0 = 0.f, a1 = 0.f, a2 = 0.f, a3 = 0.f;
        #pragma unroll 8
        for (int h = 0; h < 64; h++) {
            a0 = fmaf(Ss[h],       rW2[h * 256 + t],         a0);
            a1 = fmaf(Ss[64 + h],  rW2[(64 + h) * 256 + t],  a1);
            a2 = fmaf(Ss[128 + h], rW2[(128 + h) * 256 + t], a2);
            a3 = fmaf(Ss[192 + h], rW2[(192 + h) * 256 + t], a3);
        }
        raw[t] = rb2[t] + (a0 + a1) + (a2 + a3);
    }
    __syncthreads();

    int i = t >> 4, j = t & 15;
    out[b * 256 + t] = 0.5f * (raw[i * 16 + j] + raw[j * 16 + i]);
}

// ============================================================================
extern "C" void kernel_launch(void* const* d_in, const int* in_sizes, int n_in,
                              void* d_out, int out_size)
{
    const float* points = (const float*)d_in[0];
    const float* mW1    = (const float*)d_in[1];
    const float* mb1    = (const float*)d_in[2];
    const float* mW2    = (const float*)d_in[3];
    const float* mb2    = (const float*)d_in[4];
    const float* cW1    = (const float*)d_in[5];
    const float* cb1    = (const float*)d_in[6];
    const float* cW2    = (const float*)d_in[7];
    const float* cb2    = (const float*)d_in[8];
    const float* rW1    = (const float*)d_in[9];
    const float* rb1    = (const float*)d_in[10];
    const float* rW2    = (const float*)d_in[11];
    const float* rb2    = (const float*)d_in[12];
    float* out = (float*)d_out;

    k_metric<<<NB, 1024>>>(points, mW1, mb1, mW2, mb2, rW1, rb1);
    dim3 grid2(ND, NB);
    k_main<<<grid2, 256>>>(cW1, cb1, cW2, cb2, rW1);
    k_final<<<NB, 256>>>(rW2, rb2, out);
}

// round 8
// speedup vs baseline: 1.9011x; 1.2114x over previous
#include <cuda_runtime.h>
#include <cuda_fp16.h>
#include <cstdint>

#define NB 256   // batch
#define ND 16    // manifold dim
#define NH 128   // hidden
#define R2H 256  // 2H

// ---- scratch (device globals; no allocation) ----
__device__ float g_metric[NB * 256];          // metric[b][i*16+j]
__device__ float g_PB[NB * 256];              // points@rW1[0:16] + rb1
__device__ float g_M1[NB * ND * 256];         // M1[b][i][o]
__device__ float g_M2[NB * ND * 256];         // M2[b][j][o]
__device__ float g_Spart[NB * ND * 256];      // per-(b,i) partial hidden sums

__device__ __forceinline__ __half2 tanh2h(__half2 x) {
    uint32_t xi, yi;
    xi = *reinterpret_cast<uint32_t*>(&x);
    asm("tanh.approx.f16x2 %0, %1;" : "=r"(yi) : "r"(xi));
    __half2 y = *reinterpret_cast<__half2*>(&yi);
    return y;
}

// ============================================================================
// K1: metric + PB + M1/M2.  grid=NB, 1024 threads.  (R5 verbatim)
// ============================================================================
__global__ __launch_bounds__(1024) void k_metric(
    const float* __restrict__ points,
    const float* __restrict__ mW1, const float* __restrict__ mb1,
    const float* __restrict__ mW2, const float* __restrict__ mb2,
    const float* __restrict__ rW1, const float* __restrict__ rb1)
{
    int b = blockIdx.x;
    int t = threadIdx.x;
    int g2 = t >> 8, o = t & 255;

    __shared__ float pts[ND];
    __shared__ float mh[NH];
    __shared__ __align__(16) float part[16][256];
    __shared__ float met[256];

    // hoisted independent loads (used only at the end)
    float rwA[ND], rwB[ND];
    #pragma unroll
    for (int p = 0; p < ND; p++) {
        rwA[p] = rW1[(16 + p) * 256 + o];
        rwB[p] = rW1[(32 + p) * 256 + o];
    }

    if (t < ND) pts[t] = points[b * ND + t];
    __syncthreads();

    if (t < NH) {
        float a = mb1[t];
        #pragma unroll
        for (int p = 0; p < ND; p++) a = fmaf(pts[p], mW1[p * NH + t], a);
        mh[t] = fmaxf(a, 0.0f);
    }
    __syncthreads();

    {
        int g = t >> 6, q = t & 63;
        float4 acc = make_float4(0.f, 0.f, 0.f, 0.f);
        #pragma unroll
        for (int h = 0; h < 8; h++) {
            int hh = g * 8 + h;
            float4 w = *(const float4*)&mW2[hh * 256 + 4 * q];
            float m = mh[hh];
            acc.x = fmaf(m, w.x, acc.x);
            acc.y = fmaf(m, w.y, acc.y);
            acc.z = fmaf(m, w.z, acc.z);
            acc.w = fmaf(m, w.w, acc.w);
        }
        *(float4*)&part[g][4 * q] = acc;
    }
    __syncthreads();

    if (t < 256) {
        float a = mb2[t];
        #pragma unroll
        for (int g = 0; g < 16; g++) a += part[g][t];
        part[0][t] = a;
    }
    __syncthreads();

    if (t < 256) {
        int i = t >> 4, j = t & 15;
        float m = 0.5f * (part[0][i * 16 + j] + part[0][j * 16 + i])
                + (i == j ? 1e-6f : 0.0f);
        met[t] = m;
        g_metric[b * 256 + t] = m;
        float a = rb1[t];
        #pragma unroll
        for (int p = 0; p < ND; p++) a = fmaf(pts[p], rW1[p * 256 + t], a);
        g_PB[b * 256 + t] = a;
    }
    __syncthreads();

    #pragma unroll
    for (int ii = 0; ii < 4; ii++) {
        int i0 = g2 * 4 + ii;
        float a1 = 0.0f, a2 = 0.0f;
        #pragma unroll
        for (int p = 0; p < ND; p++) {
            float mv = met[i0 * 16 + p];
            a1 = fmaf(mv, rwA[p], a1);
            a2 = fmaf(mv, rwB[p], a2);
        }
        g_M1[(b * ND + i0) * 256 + o] = a1;
        g_M2[(b * ND + i0) * 256 + o] = a2;
    }
}

// ============================================================================
// K2: main fused kernel. One block per (i, b); 256 threads.
//   Stage A: fp16x2 christoffel MLP (HFMA2 + tanh.approx.f16x2),
//            half2 accumulator flushed to fp32 every 8 pairs; chs stored fp32.
//   Stage B: fp32, byte-for-byte the R5 (passing) version.
// ============================================================================
struct WPack { __half2 w0, w1, w2, b; };   // 16 bytes

__global__ __launch_bounds__(256) void k_main(
    const float* __restrict__ cW1, const float* __restrict__ cb1,
    const float* __restrict__ cW2, const float* __restrict__ cb2,
    const float* __restrict__ rW1)
{
    int i = blockIdx.x;   // 0..15
    int b = blockIdx.y;   // 0..255
    int t = threadIdx.x;  // 0..255

    __shared__ float met[256];
    __shared__ __align__(16) WPack   sW[NH / 2];
    __shared__ __align__(4)  __half2 sV[NH / 2];
    __shared__ __align__(16) float   chs[256];

    met[t] = g_metric[b * 256 + t];
    if (t < NH / 2) {
        int q = t;
        WPack w;
        w.w0 = __floats2half2_rn(cW1[2 * q],          cW1[2 * q + 1]);
        w.w1 = __floats2half2_rn(cW1[NH + 2 * q],     cW1[NH + 2 * q + 1]);
        w.w2 = __floats2half2_rn(cW1[2 * NH + 2 * q], cW1[2 * NH + 2 * q + 1]);
        w.b  = __floats2half2_rn(cb1[2 * q],          cb1[2 * q + 1]);
        sW[q] = w;
        sV[q] = __floats2half2_rn(cW2[2 * q], cW2[2 * q + 1]);
    }
    __syncthreads();

    // ---- Stage A: christoffel for (i, j=t>>4, k=t&15) ----
    {
        int j = t >> 4, k = t & 15;
        __half2 mij2 = __float2half2_rn(met[i * 16 + j]);
        __half2 mjk2 = __float2half2_rn(met[j * 16 + k]);
        __half2 mki2 = __float2half2_rn(met[i * 16 + k]);  // metric symmetric
        const __half2 z2 = __float2half2_rn(0.0f);

        float facc = cb2[0];
        #pragma unroll
        for (int blk = 0; blk < 8; blk++) {
            __half2 acc = z2;
            #pragma unroll
            for (int r = 0; r < 8; r++) {
                int q = blk * 8 + r;
                WPack w = sW[q];
                __half2 x = __hfma2(mij2, w.w0, w.b);
                x = __hfma2(mjk2, w.w1, x);
                x = __hfma2(mki2, w.w2, x);
                acc = __hfma2(sV[q], tanh2h(x), acc);
            }
            float2 f = __half22float2(acc);
            facc += f.x + f.y;
        }
        chs[t] = facc;
    }
    __syncthreads();

    // ---- Stage B: hidden layer of ricci net, reduced over j (fp32, R5) ----
    {
        int o = t;
        const float* rW1c = rW1 + 48 * 256;
        float rw[ND];
        #pragma unroll
        for (int k = 0; k < ND; k++) rw[k] = rW1c[k * 256 + o];

        float pm = g_PB[b * 256 + o] + g_M1[(b * ND + i) * 256 + o];
        float s = 0.0f;
        #pragma unroll 4
        for (int j = 0; j < ND; j++) {
            float a = pm + g_M2[(b * ND + j) * 256 + o];
            const float4* chr = (const float4*)&chs[j * 16];
            #pragma unroll
            for (int q = 0; q < 4; q++) {
                float4 c = chr[q];
                a = fmaf(c.x, rw[4 * q + 0], a);
                a = fmaf(c.y, rw[4 * q + 1], a);
                a = fmaf(c.z, rw[4 * q + 2], a);
                a = fmaf(c.w, rw[4 * q + 3], a);
            }
            s += fmaxf(a, 0.0f);
        }
        g_Spart[(b * ND + i) * 256 + o] = s;   // deterministic partials
    }
}

// ============================================================================
// K3: reduce partials + output GEMM + symmetrize. grid=NB, 256 threads. (R5)
// ============================================================================
__global__ __launch_bounds__(256) void k_final(
    const float* __restrict__ rW2, const float* __restrict__ rb2,
    float* __restrict__ out)
{
    int b = blockIdx.x;
    int t = threadIdx.x;
    __shared__ float Ss[256];
    __shared__ float raw[256];

    float s = 0.0f;
    #pragma unroll
    for (int i = 0; i < ND; i++) s += g_Spart[(b * ND + i) * 256 + t];
    Ss[t] = s * (1.0f / 256.0f);
    __syncthreads();

    {
        float a0 = 0.f, a1 = 0.f, a2 = 0.f, a3 = 0.f;
        #pragma unroll 8
        for (int h = 0; h < 64; h++) {
            a0 = fmaf(Ss[h],       rW2[h * 256 + t],         a0);
            a1 = fmaf(Ss[64 + h],  rW2[(64 + h) * 256 + t],  a1);
            a2 = fmaf(Ss[128 + h], rW2[(128 + h) * 256 + t], a2);
            a3 = fmaf(Ss[192 + h], rW2[(192 + h) * 256 + t], a3);
        }
        raw[t] = rb2[t] + (a0 + a1) + (a2 + a3);
    }
    __syncthreads();

    int i = t >> 4, j = t & 15;
    out[b * 256 + t] = 0.5f * (raw[i * 16 + j] + raw[j * 16 + i]);
}

// ============================================================================
extern "C" void kernel_launch(void* const* d_in, const int* in_sizes, int n_in,
                              void* d_out, int out_size)
{
    const float* points = (const float*)d_in[0];
    const float* mW1    = (const float*)d_in[1];
    const float* mb1    = (const float*)d_in[2];
    const float* mW2    = (const float*)d_in[3];
    const float* mb2    = (const float*)d_in[4];
    const float* cW1    = (const float*)d_in[5];
    const float* cb1    = (const float*)d_in[6];
    const float* cW2    = (const float*)d_in[7];
    const float* cb2    = (const float*)d_in[8];
    const float* rW1    = (const float*)d_in[9];
    const float* rb1    = (const float*)d_in[10];
    const float* rW2    = (const float*)d_in[11];
    const float* rb2    = (const float*)d_in[12];
    float* out = (float*)d_out;

    k_metric<<<NB, 1024>>>(points, mW1, mb1, mW2, mb2, rW1, rb1);
    dim3 grid2(ND, NB);
    k_main<<<grid2, 256>>>(cW1, cb1, cW2, cb2, rW1);
    k_final<<<NB, 256>>>(rW2, rb2, out);
}

// round 9
// speedup vs baseline: 2.0940x; 1.1015x over previous
#include <cuda_runtime.h>
#include <cuda_fp16.h>
#include <cstdint>

#define NB 256   // batch
#define ND 16    // manifold dim
#define NH 128   // hidden
#define R2H 256  // 2H
#define IPB 4    // i's per block in k_main

// ---- scratch (device globals; no allocation) ----
__device__ float g_metric[NB * 256];          // metric[b][i*16+j]
__device__ float g_PB[NB * 256];              // points@rW1[0:16] + rb1
__device__ float g_M1[NB * ND * 256];         // M1[b][i][o]
__device__ float g_M2[NB * ND * 256];         // M2[b][j][o]
__device__ float g_Spart[NB * ND * 256];      // per-(b,i) partial hidden sums

__device__ __forceinline__ __half2 tanh2h(__half2 x) {
    uint32_t xi, yi;
    xi = *reinterpret_cast<uint32_t*>(&x);
    asm("tanh.approx.f16x2 %0, %1;" : "=r"(yi) : "r"(xi));
    __half2 y = *reinterpret_cast<__half2*>(&yi);
    return y;
}
__device__ __forceinline__ __half2 u2h2(uint32_t u) {
    return *reinterpret_cast<__half2*>(&u);
}

// ============================================================================
// K1: metric + PB + M1/M2.  grid=NB, 1024 threads.  (R5/R7 verbatim)
// ============================================================================
__global__ __launch_bounds__(1024) void k_metric(
    const float* __restrict__ points,
    const float* __restrict__ mW1, const float* __restrict__ mb1,
    const float* __restrict__ mW2, const float* __restrict__ mb2,
    const float* __restrict__ rW1, const float* __restrict__ rb1)
{
    int b = blockIdx.x;
    int t = threadIdx.x;
    int g2 = t >> 8, o = t & 255;

    __shared__ float pts[ND];
    __shared__ float mh[NH];
    __shared__ __align__(16) float part[16][256];
    __shared__ float met[256];

    float rwA[ND], rwB[ND];
    #pragma unroll
    for (int p = 0; p < ND; p++) {
        rwA[p] = rW1[(16 + p) * 256 + o];
        rwB[p] = rW1[(32 + p) * 256 + o];
    }

    if (t < ND) pts[t] = points[b * ND + t];
    __syncthreads();

    if (t < NH) {
        float a = mb1[t];
        #pragma unroll
        for (int p = 0; p < ND; p++) a = fmaf(pts[p], mW1[p * NH + t], a);
        mh[t] = fmaxf(a, 0.0f);
    }
    __syncthreads();

    {
        int g = t >> 6, q = t & 63;
        float4 acc = make_float4(0.f, 0.f, 0.f, 0.f);
        #pragma unroll
        for (int h = 0; h < 8; h++) {
            int hh = g * 8 + h;
            float4 w = *(const float4*)&mW2[hh * 256 + 4 * q];
            float m = mh[hh];
            acc.x = fmaf(m, w.x, acc.x);
            acc.y = fmaf(m, w.y, acc.y);
            acc.z = fmaf(m, w.z, acc.z);
            acc.w = fmaf(m, w.w, acc.w);
        }
        *(float4*)&part[g][4 * q] = acc;
    }
    __syncthreads();

    if (t < 256) {
        float a = mb2[t];
        #pragma unroll
        for (int g = 0; g < 16; g++) a += part[g][t];
        part[0][t] = a;
    }
    __syncthreads();

    if (t < 256) {
        int i = t >> 4, j = t & 15;
        float m = 0.5f * (part[0][i * 16 + j] + part[0][j * 16 + i])
                + (i == j ? 1e-6f : 0.0f);
        met[t] = m;
        g_metric[b * 256 + t] = m;
        float a = rb1[t];
        #pragma unroll
        for (int p = 0; p < ND; p++) a = fmaf(pts[p], rW1[p * 256 + t], a);
        g_PB[b * 256 + t] = a;
    }
    __syncthreads();

    #pragma unroll
    for (int ii = 0; ii < 4; ii++) {
        int i0 = g2 * 4 + ii;
        float a1 = 0.0f, a2 = 0.0f;
        #pragma unroll
        for (int p = 0; p < ND; p++) {
            float mv = met[i0 * 16 + p];
            a1 = fmaf(mv, rwA[p], a1);
            a2 = fmaf(mv, rwB[p], a2);
        }
        g_M1[(b * ND + i0) * 256 + o] = a1;
        g_M2[(b * ND + i0) * 256 + o] = a2;
    }
}

// ============================================================================
// K2: main fused kernel. One block per (i-quad, b); 256 threads.
//   Stage A: fp16x2 MLP for 4 i's at once — weight LDS amortized 4x.
//   Stage B: fp16 HFMA2 dot products for 4 i's; fp32 pm/m2/relu/sum.
// ============================================================================
struct WPack { __half2 w0, w1, w2, b; };   // 16 bytes

__global__ __launch_bounds__(256) void k_main(
    const float* __restrict__ cW1, const float* __restrict__ cb1,
    const float* __restrict__ cW2, const float* __restrict__ cb2,
    const float* __restrict__ rW1)
{
    int i0 = blockIdx.x * IPB;  // 0,4,8,12
    int b  = blockIdx.y;        // 0..255
    int t  = threadIdx.x;       // 0..255

    __shared__ float met[256];
    __shared__ __align__(16) WPack   sW[NH / 2];
    __shared__ __align__(4)  __half2 sV[NH / 2];
    __shared__ __align__(16) __half  chs[IPB][256];

    met[t] = g_metric[b * 256 + t];
    if (t < NH / 2) {
        int q = t;
        WPack w;
        w.w0 = __floats2half2_rn(cW1[2 * q],          cW1[2 * q + 1]);
        w.w1 = __floats2half2_rn(cW1[NH + 2 * q],     cW1[NH + 2 * q + 1]);
        w.w2 = __floats2half2_rn(cW1[2 * NH + 2 * q], cW1[2 * NH + 2 * q + 1]);
        w.b  = __floats2half2_rn(cb1[2 * q],          cb1[2 * q + 1]);
        sW[q] = w;
        sV[q] = __floats2half2_rn(cW2[2 * q], cW2[2 * q + 1]);
    }
    __syncthreads();

    // ---- Stage A: christoffel for (i0..i0+3, j=t>>4, k=t&15) ----
    {
        int j = t >> 4, k = t & 15;
        __half2 mjk2 = __float2half2_rn(met[j * 16 + k]);
        __half2 mij2[IPB], mki2[IPB];
        #pragma unroll
        for (int ii = 0; ii < IPB; ii++) {
            mij2[ii] = __float2half2_rn(met[(i0 + ii) * 16 + j]);
            mki2[ii] = __float2half2_rn(met[(i0 + ii) * 16 + k]);  // symmetric
        }
        const __half2 z2 = __float2half2_rn(0.0f);

        float facc[IPB];
        #pragma unroll
        for (int ii = 0; ii < IPB; ii++) facc[ii] = cb2[0];

        #pragma unroll
        for (int blk = 0; blk < 8; blk++) {
            __half2 acc[IPB];
            #pragma unroll
            for (int ii = 0; ii < IPB; ii++) acc[ii] = z2;
            #pragma unroll
            for (int r = 0; r < 8; r++) {
                int q = blk * 8 + r;
                WPack w = sW[q];
                __half2 v = sV[q];
                #pragma unroll
                for (int ii = 0; ii < IPB; ii++) {
                    __half2 x = __hfma2(mij2[ii], w.w0, w.b);
                    x = __hfma2(mjk2, w.w1, x);
                    x = __hfma2(mki2[ii], w.w2, x);
                    acc[ii] = __hfma2(v, tanh2h(x), acc[ii]);
                }
            }
            #pragma unroll
            for (int ii = 0; ii < IPB; ii++) {
                float2 f = __half22float2(acc[ii]);
                facc[ii] += f.x + f.y;
            }
        }
        #pragma unroll
        for (int ii = 0; ii < IPB; ii++)
            chs[ii][t] = __float2half(facc[ii]);
    }
    __syncthreads();

    // ---- Stage B: hidden layer of ricci net, reduced over j, 4 i's ----
    {
        int o = t;
        const float* rW1c = rW1 + 48 * 256;
        __half2 rwh[8];
        #pragma unroll
        for (int q = 0; q < 8; q++)
            rwh[q] = __floats2half2_rn(rW1c[(2 * q) * 256 + o],
                                       rW1c[(2 * q + 1) * 256 + o]);

        float pm[IPB], s[IPB];
        float pb = g_PB[b * 256 + o];
        #pragma unroll
        for (int ii = 0; ii < IPB; ii++) {
            pm[ii] = pb + g_M1[(b * ND + i0 + ii) * 256 + o];
            s[ii] = 0.0f;
        }
        const __half2 z2 = __float2half2_rn(0.0f);

        #pragma unroll 4
        for (int j = 0; j < ND; j++) {
            float m2 = g_M2[(b * ND + j) * 256 + o];
            #pragma unroll
            for (int ii = 0; ii < IPB; ii++) {
                const uint4* cp = (const uint4*)&chs[ii][j * 16];
                uint4 u0 = cp[0];
                uint4 u1 = cp[1];
                __half2 acc = z2;
                acc = __hfma2(u2h2(u0.x), rwh[0], acc);
                acc = __hfma2(u2h2(u0.y), rwh[1], acc);
                acc = __hfma2(u2h2(u0.z), rwh[2], acc);
                acc = __hfma2(u2h2(u0.w), rwh[3], acc);
                acc = __hfma2(u2h2(u1.x), rwh[4], acc);
                acc = __hfma2(u2h2(u1.y), rwh[5], acc);
                acc = __hfma2(u2h2(u1.z), rwh[6], acc);
                acc = __hfma2(u2h2(u1.w), rwh[7], acc);
                float2 f = __half22float2(acc);
                float a = pm[ii] + m2 + f.x + f.y;
                s[ii] += fmaxf(a, 0.0f);
            }
        }
        #pragma unroll
        for (int ii = 0; ii < IPB; ii++)
            g_Spart[(b * ND + i0 + ii) * 256 + o] = s[ii];
    }
}

// ============================================================================
// K3: reduce partials + output GEMM + symmetrize. grid=NB, 256 threads. (R5)
// ============================================================================
__global__ __launch_bounds__(256) void k_final(
    const float* __restrict__ rW2, const float* __restrict__ rb2,
    float* __restrict__ out)
{
    int b = blockIdx.x;
    int t = threadIdx.x;
    __shared__ float Ss[256];
    __shared__ float raw[256];

    float s = 0.0f;
    #pragma unroll
    for (int i = 0; i < ND; i++) s += g_Spart[(b * ND + i) * 256 + t];
    Ss[t] = s * (1.0f / 256.0f);
    __syncthreads();

    {
        float a0 = 0.f, a1 = 0.f, a2 = 0.f, a3 = 0.f;
        #pragma unroll 8
        for (int h = 0; h < 64; h++) {
            a0 = fmaf(Ss[h],       rW2[h * 256 + t],         a0);
            a1 = fmaf(Ss[64 + h],  rW2[(64 + h) * 256 + t],  a1);
            a2 = fmaf(Ss[128 + h], rW2[(128 + h) * 256 + t], a2);
            a3 = fmaf(Ss[192 + h], rW2[(192 + h) * 256 + t], a3);
        }
        raw[t] = rb2[t] + (a0 + a1) + (a2 + a3);
    }
    __syncthreads();

    int i = t >> 4, j = t & 15;
    out[b * 256 + t] = 0.5f * (raw[i * 16 + j] + raw[j * 16 + i]);
}

// ============================================================================
extern "C" void kernel_launch(void* const* d_in, const int* in_sizes, int n_in,
                              void* d_out, int out_size)
{
    const float* points = (const float*)d_in[0];
    const float* mW1    = (const float*)d_in[1];
    const float* mb1    = (const float*)d_in[2];
    const float* mW2    = (const float*)d_in[3];
    const float* mb2    = (const float*)d_in[4];
    const float* cW1    = (const float*)d_in[5];
    const float* cb1    = (const float*)d_in[6];
    const float* cW2    = (const float*)d_in[7];
    const float* cb2    = (const float*)d_in[8];
    const float* rW1    = (const float*)d_in[9];
    const float* rb1    = (const float*)d_in[10];
    const float* rW2    = (const float*)d_in[11];
    const float* rb2    = (const float*)d_in[12];
    float* out = (float*)d_out;

    k_metric<<<NB, 1024>>>(points, mW1, mb1, mW2, mb2, rW1, rb1);
    dim3 grid2(ND / IPB, NB);
    k_main<<<grid2, 256>>>(cW1, cb1, cW2, cb2, rW1);
    k_final<<<NB, 256>>>(rW2, rb2, out);
}